// round 15
// baseline (speedup 1.0000x reference)
#include <cuda_runtime.h>

#define TS    100
#define BB    256
#define DOBS  64
#define DFEAT 512
#define DLAT  512
#define DOUTD 64
#define NB    128   // persistent blocks (1/SM, all resident)

// d_out layout (element offsets): outs, hs, thetas, ys, delta_outs
#define OUTS_OFF 0
#define HS_OFF   (TS*BB*DOUTD)
#define TH_OFF   (HS_OFF + TS*BB*DLAT)
#define YS_OFF   (TH_OFF + TS*BB*DLAT)
#define DO_OFF   (YS_OFF + TS*BB*DLAT)

typedef unsigned long long ull;

__device__ __forceinline__ ull fma2(ull a, ull b, ull c) {
    ull d; asm("fma.rn.f32x2 %0, %1, %2, %3;" : "=l"(d) : "l"(a), "l"(b), "l"(c)); return d;
}
__device__ __forceinline__ ull add2(ull a, ull b) {
    ull d; asm("add.rn.f32x2 %0, %1, %2;" : "=l"(d) : "l"(a), "l"(b)); return d;
}
__device__ __forceinline__ ull pack2s(float f) {   // (f, f)
    ull r; asm("mov.b64 %0, {%1, %1};" : "=l"(r) : "f"(f)); return r;
}
__device__ __forceinline__ float2 unpack2(ull v) {
    float2 f; asm("mov.b64 {%0, %1}, %2;" : "=f"(f.x), "=f"(f.y) : "l"(v)); return f;
}

// persistent state across steps
__device__ float g_x[BB * DFEAT];    // x(t)
__device__ float g_xin[BB * DOBS];   // x_in(t)

// grid barrier
__device__ unsigned g_bar_cnt = 0;
__device__ volatile unsigned g_bar_gen = 0;

union SmemU {
    struct {                       // phase GEMM tiles, quad-buffered (R14 layout)
        float As[4][32][36];       // [k][row], non-duplicated (18 KB)
        float W12[4][32][64];      // interleaved (w1,w1,w2,w2) pairs (32 KB)
    } ph;
    struct {                       // out + prep staging
        float ysm[2][512];
        float opred[2][8][16][4];  // W_out K-partials
        float pred[2][4][512];     // W_pre o-partials
        float outm[2][64];
        float xinm[2][64];
    } op;
};
#define SMEM_BYTES ((int)sizeof(SmemU))

// split grid barrier (release/acquire identical to the R10-R14 fused one)
__device__ __forceinline__ void grid_arrive(int tid, unsigned* sgen) {
    __syncthreads();
    if (tid == 0) {
        unsigned gen = g_bar_gen;
        *sgen = gen;
        __threadfence();
        if (atomicAdd(&g_bar_cnt, 1u) == NB - 1) {
            g_bar_cnt = 0;
            __threadfence();
            g_bar_gen = gen + 1;
        }
    }
    __syncthreads();
}
__device__ __forceinline__ void grid_wait(int tid, const unsigned* sgen) {
    if (tid == 0) {
        unsigned gen = *sgen;
        while (g_bar_gen == gen) {}
        __threadfence();
    }
    __syncthreads();
}

// ---------------------------------------------------------------------------
// Warp-specialized dual-GEMM stage range [s_begin, s_end), quad-buffered,
// sync every 2 stages. R14 layout/store pattern verbatim. Per-element FMA
// sequence (kk ascending, stage partials folded in ascending stage order
// across calls) BIT-IDENTICAL to R12/R14.
// ---------------------------------------------------------------------------
__device__ __forceinline__ void phase_stages(
    SmemU& sm, int m0, int n0, int s_begin, int s_end,
    const float* __restrict__ W1, const float* __restrict__ W2,
    const float* __restrict__ h_src,
    ull* acc1, ull* acc2)
{
    const int tid = threadIdx.x;
    const bool consumer = (tid < 128);
    const int r0 = ((tid & 127) >> 4) * 4;   // rows r0..r0+3
    const int c0 = (tid & 15) * 2;           // cols c0, c0+1
    const int ptid = tid & 127;

    auto aSrc = [&](int s, int slot) -> const float* {
        const int k0 = s * 32;
        const int row = slot >> 3, q = slot & 7;
        const float* src; int kb;
        if (k0 < 512) { src = g_x;   kb = k0; }
        else          { src = h_src; kb = k0 - 512; }
        return &src[(size_t)(m0 + row) * 512 + kb + q * 4];
    };
    auto stageLoad = [&](int s, float4* aR, float4* w1R, float4* w2R) {
#pragma unroll
        for (int i = 0; i < 2; i++) {
            const int slot = ptid + i * 128;
            const int k = slot >> 3, q = slot & 7;
            aR[i]  = *(const float4*)aSrc(s, slot);
            w1R[i] = *(const float4*)&W1[(size_t)(s * 32 + k) * 512 + n0 + q * 4];
            w2R[i] = *(const float4*)&W2[(size_t)(s * 32 + k) * 512 + n0 + q * 4];
        }
    };
    auto stageStore = [&](int buf, const float4* aR, const float4* w1R, const float4* w2R) {
#pragma unroll
        for (int i = 0; i < 2; i++) {
            const int slot = ptid + i * 128;
            const int row = slot >> 3, q = slot & 7;
            sm.ph.As[buf][q * 4 + 0][row] = aR[i].x;
            sm.ph.As[buf][q * 4 + 1][row] = aR[i].y;
            sm.ph.As[buf][q * 4 + 2][row] = aR[i].z;
            sm.ph.As[buf][q * 4 + 3][row] = aR[i].w;
            *(float4*)&sm.ph.W12[buf][row][q * 8 + 0] =
                make_float4(w1R[i].x, w1R[i].y, w2R[i].x, w2R[i].y);
            *(float4*)&sm.ph.W12[buf][row][q * 8 + 4] =
                make_float4(w1R[i].z, w1R[i].w, w2R[i].z, w2R[i].w);
        }
    };
    auto compute = [&](int buf) {
        ull p1[4] = {0ull, 0ull, 0ull, 0ull};
        ull p2[4] = {0ull, 0ull, 0ull, 0ull};
#pragma unroll
        for (int kk = 0; kk < 32; kk++) {
            float4 a = *(const float4*)&sm.ph.As[buf][kk][r0];
            ulonglong2 w = *(const ulonglong2*)&sm.ph.W12[buf][kk][2 * c0];
            ull a0 = pack2s(a.x), a1 = pack2s(a.y);
            ull a2 = pack2s(a.z), a3 = pack2s(a.w);
            p1[0] = fma2(a0, w.x, p1[0]);
            p2[0] = fma2(a0, w.y, p2[0]);
            p1[1] = fma2(a1, w.x, p1[1]);
            p2[1] = fma2(a1, w.y, p2[1]);
            p1[2] = fma2(a2, w.x, p1[2]);
            p2[2] = fma2(a2, w.y, p2[2]);
            p1[3] = fma2(a3, w.x, p1[3]);
            p2[3] = fma2(a3, w.y, p2[3]);
        }
#pragma unroll
        for (int i = 0; i < 4; i++) {
            acc1[i] = add2(acc1[i], p1[i]);
            acc2[i] = add2(acc2[i], p2[i]);
        }
    };

    // prologue: producers fill stages s_begin, s_begin+1
    if (!consumer) {
        float4 aR[2], w1R[2], w2R[2];
        stageLoad(s_begin, aR, w1R, w2R);
        stageStore(s_begin & 3, aR, w1R, w2R);
        stageLoad(s_begin + 1, aR, w1R, w2R);
        stageStore((s_begin + 1) & 3, aR, w1R, w2R);
    }
    __syncthreads();

    for (int s = s_begin; s < s_end; s += 2) {
        if (consumer) {
            compute(s & 3);
            compute((s + 1) & 3);
        } else {
            if (s + 2 < s_end) {
                float4 aR[2], w1R[2], w2R[2];
                float4 aS[2], w1S[2], w2S[2];
                stageLoad(s + 2, aR, w1R, w2R);
                stageLoad(s + 3, aS, w1S, w2S);
                stageStore((s + 2) & 3, aR, w1R, w2R);
                stageStore((s + 3) & 3, aS, w1S, w2S);
            }
        }
        __syncthreads();
    }
}

// fp64 epilogues (R4-exact), consumers only
__device__ __forceinline__ void epilogue0(
    int m0, int n0, bool zero_h, const ull* acc1, const ull* acc2,
    const float* __restrict__ b1, const float* __restrict__ b2,
    const float* __restrict__ noise_t, const float* __restrict__ h_src,
    float* __restrict__ out1, float* __restrict__ out_th)
{
    const int tid = threadIdx.x;
    const int r0 = ((tid & 127) >> 4) * 4;
    const int c0 = (tid & 15) * 2;
#pragma unroll
    for (int i = 0; i < 4; i++) {
        const int b = m0 + r0 + i;
        float2 v1 = unpack2(acc1[i]);
        float2 v2 = unpack2(acc2[i]);
        float a1v[2] = {v1.x, v1.y};
        float a2v[2] = {v2.x, v2.y};
#pragma unroll
        for (int c = 0; c < 2; c++) {
            const int n = n0 + c0 + c;
            double z = (double)a1v[c] + (double)b1[n]
                     + (double)noise_t[b * DLAT + n];
            float th = (z > 0.0) ? 1.f : 0.f;
            double g  = (z > 0.0) ? tanh(z) : 0.0;
            double hp = zero_h ? 0.0 : (double)h_src[b * DLAT + n];
            double rl = (double)a2v[c] + (double)b2[n];
            float h = (float)(g * tanh(rl) + (1.0 - g) * hp);
            out1[b * DLAT + n]   = h;
            out_th[b * DLAT + n] = th;
        }
    }
}
__device__ __forceinline__ void epilogue1(
    int m0, int n0, const ull* acc1, const ull* acc2,
    const float* __restrict__ b1, const float* __restrict__ b2,
    float* __restrict__ out1)
{
    const int tid = threadIdx.x;
    const int r0 = ((tid & 127) >> 4) * 4;
    const int c0 = (tid & 15) * 2;
#pragma unroll
    for (int i = 0; i < 4; i++) {
        const int b = m0 + r0 + i;
        float2 v1 = unpack2(acc1[i]);
        float2 v2 = unpack2(acc2[i]);
        float a1v[2] = {v1.x, v1.y};
        float a2v[2] = {v2.x, v2.y};
#pragma unroll
        for (int c = 0; c < 2; c++) {
            const int n = n0 + c0 + c;
            double p = (double)a1v[c] + (double)b1[n];
            double o = (double)a2v[c] + (double)b2[n];
            float y = (float)(tanh(p) / (1.0 + exp(-o)));
            out1[b * DLAT + n] = y;
        }
    }
}

// ---------------------------------------------------------------------------
// Persistent megakernel.
// ---------------------------------------------------------------------------
__global__ __launch_bounds__(256, 1) void mega_kernel(
    const float* __restrict__ obs,   const float* __restrict__ smask,
    const float* __restrict__ noise,
    const float* __restrict__ W_pre, const float* __restrict__ b_pre,
    const float* __restrict__ Wg,    const float* __restrict__ bg,
    const float* __restrict__ Wr,    const float* __restrict__ br,
    const float* __restrict__ Wp,    const float* __restrict__ bp,
    const float* __restrict__ Wo,    const float* __restrict__ bo,
    const float* __restrict__ W_out, const float* __restrict__ b_out,
    float* __restrict__ outs, float* __restrict__ hs, float* __restrict__ ths,
    float* __restrict__ ys,   float* __restrict__ dos_)
{
    extern __shared__ char smem_raw[];
    SmemU& sm = *(SmemU*)smem_raw;
    __shared__ unsigned sgen;
    const int tid = threadIdx.x;
    const int blk = blockIdx.x;
    const int m0 = (blk >> 4) * 32;
    const int n0 = (blk & 15) * 32;
    const int b0 = blk * 2;

    // out (+ next-step prep), split-K/split-o reductions (verbatim R11-R14)
    auto do_out_prep = [&](int t, bool do_out, bool do_prep, bool first) {
        auto& op = sm.op;
        if (do_out) {
            const float* y_t = ys + (size_t)t * BB * DLAT;
            {
                int r = tid >> 7, q = tid & 127;
                *(float4*)&op.ysm[r][q * 4] =
                    *(const float4*)&y_t[(size_t)(b0 + r) * 512 + q * 4];
            }
            __syncthreads();
            {
                const int r  = tid >> 7;
                const int fg = (tid >> 4) & 7;
                const int og = tid & 15;
                float4 a = make_float4(0.f, 0.f, 0.f, 0.f);
#pragma unroll 8
                for (int j = 0; j < 64; j++) {
                    const int f = fg * 64 + j;
                    float4 w = *(const float4*)&W_out[(size_t)f * 64 + og * 4];
                    float yv = op.ysm[r][f];
                    a.x += yv * w.x; a.y += yv * w.y;
                    a.z += yv * w.z; a.w += yv * w.w;
                }
                *(float4*)op.opred[r][fg][og] = a;
            }
            __syncthreads();
            if (tid < 128) {
                const int r = tid >> 6, o = tid & 63;
                const int og = o >> 2, c = o & 3;
                float tot = 0.f;
#pragma unroll
                for (int fg = 0; fg < 8; fg++)
                    tot += op.opred[r][fg][og][c];
                tot += b_out[o];
                const int b = b0 + r;
                float outv = g_xin[b * 64 + o] + tot;
                outs[(size_t)t * BB * 64 + b * 64 + o] = outv;
                dos_[(size_t)t * BB * 64 + b * 64 + o] = tot;
                op.outm[r][o] = outv;
            }
            __syncthreads();
        }
        if (do_prep) {
            const int tp = first ? 0 : t + 1;
            if (tid < 128) {
                const int r = tid >> 6, o = tid & 63;
                const int b = b0 + r;
                float m = first ? 1.f
                                : ((smask[(size_t)tp * BB + b] < 0.5f) ? 1.f : 0.f);
                float xin = (m != 0.f) ? obs[(size_t)tp * BB * 64 + b * 64 + o]
                                       : op.outm[r][o];
                g_xin[b * 64 + o] = xin;
                op.xinm[r][o] = xin;
            }
            __syncthreads();
            {
                const int r2 = tid >> 7;
                const int oc = (tid >> 5) & 3;
                const int fg = tid & 31;
                const int f0 = fg * 16;
                float4 a[4];
#pragma unroll
                for (int q = 0; q < 4; q++) a[q] = make_float4(0.f, 0.f, 0.f, 0.f);
#pragma unroll 4
                for (int j = 0; j < 16; j++) {
                    const int o = oc * 16 + j;
                    float xv = op.xinm[r2][o];
#pragma unroll
                    for (int q = 0; q < 4; q++) {
                        float4 w = *(const float4*)&W_pre[(size_t)o * 512 + f0 + q * 4];
                        a[q].x += xv * w.x; a[q].y += xv * w.y;
                        a[q].z += xv * w.z; a[q].w += xv * w.w;
                    }
                }
#pragma unroll
                for (int q = 0; q < 4; q++)
                    *(float4*)&op.pred[r2][oc][f0 + q * 4] = a[q];
            }
            __syncthreads();
            {
                const int r = tid >> 7;
                const int f4 = (tid & 127) * 4;
#pragma unroll
                for (int j = 0; j < 4; j++) {
                    double s = 0.0;
#pragma unroll
                    for (int oc = 0; oc < 4; oc++)
                        s += (double)op.pred[r][oc][f4 + j];
                    g_x[(size_t)(b0 + r) * 512 + f4 + j] =
                        (float)tanh(s + (double)b_pre[f4 + j]);
                }
            }
        }
    };

    do_out_prep(0, false, true, true);
    grid_arrive(tid, &sgen);
    grid_wait(tid, &sgen);

    ull acc1[4], acc2[4];

    for (int t = 0; t < TS; t++) {
        const float* hprev = hs + (size_t)(t - 1) * BB * DLAT;  // not deref'd at t==0
        float* ht  = hs  + (size_t)t * BB * DLAT;
        float* tht = ths + (size_t)t * BB * DLAT;
        float* yt  = ys  + (size_t)t * BB * DLAT;

        // ---- phase 0 (full stage range; 16 stages at t==0) ----
#pragma unroll
        for (int i = 0; i < 4; i++) { acc1[i] = 0ull; acc2[i] = 0ull; }
        phase_stages(sm, m0, n0, 0, (t == 0) ? 16 : 32, Wg, Wr, hprev, acc1, acc2);
        if (tid < 128)
            epilogue0(m0, n0, t == 0, acc1, acc2, bg, br,
                      noise + (size_t)t * BB * DLAT, hprev, ht, tht);

        // ---- barrier 1 (h ready), overlapped with phase 1 x-half ----
        grid_arrive(tid, &sgen);
#pragma unroll
        for (int i = 0; i < 4; i++) { acc1[i] = 0ull; acc2[i] = 0ull; }
        phase_stages(sm, m0, n0, 0, 16, Wp, Wo, nullptr, acc1, acc2);  // x-half
        grid_wait(tid, &sgen);
        phase_stages(sm, m0, n0, 16, 32, Wp, Wo, ht, acc1, acc2);      // h-half
        if (tid < 128)
            epilogue1(m0, n0, acc1, acc2, bp, bo, yt);

        // ---- barrier 2 (y ready) ----
        grid_arrive(tid, &sgen);
        grid_wait(tid, &sgen);

        do_out_prep(t, true, t + 1 < TS, false);

        // ---- barrier 3 (x(t+1) ready) ----
        grid_arrive(tid, &sgen);
        grid_wait(tid, &sgen);
    }
}

// ---------------------------------------------------------------------------
extern "C" void kernel_launch(void* const* d_in, const int* in_sizes, int n_in,
                              void* d_out, int out_size)
{
    (void)in_sizes; (void)n_in; (void)out_size;
    const float* obs   = (const float*)d_in[0];
    const float* smask = (const float*)d_in[1];
    const float* noise = (const float*)d_in[2];
    const float* W_pre = (const float*)d_in[3];
    const float* b_pre = (const float*)d_in[4];
    const float* Wg    = (const float*)d_in[5];
    const float* bg    = (const float*)d_in[6];
    const float* Wr    = (const float*)d_in[7];
    const float* br    = (const float*)d_in[8];
    const float* Wp    = (const float*)d_in[9];
    const float* bp    = (const float*)d_in[10];
    const float* Wo    = (const float*)d_in[11];
    const float* bo    = (const float*)d_in[12];
    const float* W_out = (const float*)d_in[13];
    const float* b_out = (const float*)d_in[14];

    float* out  = (float*)d_out;
    float* outs = out + OUTS_OFF;
    float* hs   = out + HS_OFF;
    float* ths  = out + TH_OFF;
    float* ys   = out + YS_OFF;
    float* dos_ = out + DO_OFF;

    cudaFuncSetAttribute(mega_kernel,
                         cudaFuncAttributeMaxDynamicSharedMemorySize, SMEM_BYTES);

    mega_kernel<<<NB, 256, SMEM_BYTES>>>(obs, smask, noise,
                                         W_pre, b_pre, Wg, bg, Wr, br,
                                         Wp, bp, Wo, bo, W_out, b_out,
                                         outs, hs, ths, ys, dos_);
}

// round 16
// speedup vs baseline: 1.0827x; 1.0827x over previous
#include <cuda_runtime.h>

#define TS    100
#define BB    256
#define DOBS  64
#define DFEAT 512
#define DLAT  512
#define DOUTD 64
#define NB    128   // persistent blocks (1/SM, all resident)

// d_out layout (element offsets): outs, hs, thetas, ys, delta_outs
#define OUTS_OFF 0
#define HS_OFF   (TS*BB*DOUTD)
#define TH_OFF   (HS_OFF + TS*BB*DLAT)
#define YS_OFF   (TH_OFF + TS*BB*DLAT)
#define DO_OFF   (YS_OFF + TS*BB*DLAT)

typedef unsigned long long ull;

__device__ __forceinline__ ull fma2(ull a, ull b, ull c) {
    ull d; asm("fma.rn.f32x2 %0, %1, %2, %3;" : "=l"(d) : "l"(a), "l"(b), "l"(c)); return d;
}
__device__ __forceinline__ ull add2(ull a, ull b) {
    ull d; asm("add.rn.f32x2 %0, %1, %2;" : "=l"(d) : "l"(a), "l"(b)); return d;
}
__device__ __forceinline__ ull pack2s(float f) {   // (f, f)
    ull r; asm("mov.b64 %0, {%1, %1};" : "=l"(r) : "f"(f)); return r;
}
__device__ __forceinline__ float2 unpack2(ull v) {
    float2 f; asm("mov.b64 {%0, %1}, %2;" : "=f"(f.x), "=f"(f.y) : "l"(v)); return f;
}

// persistent state across steps
__device__ float g_x[BB * DFEAT];    // x(t)
__device__ float g_xin[BB * DOBS];   // x_in(t)

// grid barrier
__device__ unsigned g_bar_cnt = 0;
__device__ volatile unsigned g_bar_gen = 0;

union SmemU {
    struct {                       // phase GEMM tiles, quad-buffered (R14 layout)
        float As[4][32][36];       // [k][row], non-duplicated (18 KB)
        float W12[4][32][64];      // interleaved (w1,w1,w2,w2) pairs (32 KB)
        ull  h1[4][128];           // acc handoff, [i][ptid] (4 KB)
        ull  h2[4][128];           // (4 KB)
    } ph;
    struct {                       // out + prep staging
        float ysm[2][512];
        float opred[2][8][16][4];  // W_out K-partials
        float pred[2][4][512];     // W_pre o-partials
        float outm[2][64];
        float xinm[2][64];
    } op;
};
#define SMEM_BYTES ((int)sizeof(SmemU))

__device__ __forceinline__ void grid_sync(int tid) {
    __syncthreads();
    if (tid == 0) {
        unsigned gen = g_bar_gen;
        __threadfence();
        if (atomicAdd(&g_bar_cnt, 1u) == NB - 1) {
            g_bar_cnt = 0;
            __threadfence();
            g_bar_gen = gen + 1;
        } else {
            while (g_bar_gen == gen) {}
            __threadfence();
        }
    }
    __syncthreads();
}

// ---------------------------------------------------------------------------
// Warp-specialized dual-GEMM phase, quad-buffered (sync every 2 stages) —
// verbatim R14 pipeline. Per-element FMA sequence BIT-IDENTICAL to R12/R14.
// Epilogue: accs handed to smem, then ALL 256 threads split the fp64 work
// (same double-precision expression per element -> bit-identical results).
// ---------------------------------------------------------------------------
template <int PHASE>
__device__ void do_phase(SmemU& sm, int blk, bool zero_h,
                         const float* __restrict__ W1, const float* __restrict__ b1,
                         const float* __restrict__ W2, const float* __restrict__ b2,
                         const float* __restrict__ noise_t,
                         const float* __restrict__ h_src,
                         float* __restrict__ out1, float* __restrict__ out_th)
{
    const int tid = threadIdx.x;
    const int m0 = (blk >> 4) * 32;
    const int n0 = (blk & 15) * 32;
    const int nstage = zero_h ? 16 : 32;
    const bool consumer = (tid < 128);

    const int r0 = ((tid & 127) >> 4) * 4;   // rows r0..r0+3
    const int c0 = (tid & 15) * 2;           // cols c0, c0+1
    const int ptid = tid & 127;

    ull acc1[4] = {0ull, 0ull, 0ull, 0ull};
    ull acc2[4] = {0ull, 0ull, 0ull, 0ull};

    auto aSrc = [&](int s, int slot) -> const float* {
        const int k0 = s * 32;
        const int row = slot >> 3, q = slot & 7;
        const float* src; int kb;
        if (k0 < 512) { src = g_x;   kb = k0; }
        else          { src = h_src; kb = k0 - 512; }
        return &src[(size_t)(m0 + row) * 512 + kb + q * 4];
    };
    auto stageLoad = [&](int s, float4* aR, float4* w1R, float4* w2R) {
#pragma unroll
        for (int i = 0; i < 2; i++) {
            const int slot = ptid + i * 128;
            const int k = slot >> 3, q = slot & 7;
            aR[i]  = *(const float4*)aSrc(s, slot);
            w1R[i] = *(const float4*)&W1[(size_t)(s * 32 + k) * 512 + n0 + q * 4];
            w2R[i] = *(const float4*)&W2[(size_t)(s * 32 + k) * 512 + n0 + q * 4];
        }
    };
    auto stageStore = [&](int buf, const float4* aR, const float4* w1R, const float4* w2R) {
#pragma unroll
        for (int i = 0; i < 2; i++) {
            const int slot = ptid + i * 128;
            const int row = slot >> 3, q = slot & 7;
            sm.ph.As[buf][q * 4 + 0][row] = aR[i].x;
            sm.ph.As[buf][q * 4 + 1][row] = aR[i].y;
            sm.ph.As[buf][q * 4 + 2][row] = aR[i].z;
            sm.ph.As[buf][q * 4 + 3][row] = aR[i].w;
            *(float4*)&sm.ph.W12[buf][row][q * 8 + 0] =
                make_float4(w1R[i].x, w1R[i].y, w2R[i].x, w2R[i].y);
            *(float4*)&sm.ph.W12[buf][row][q * 8 + 4] =
                make_float4(w1R[i].z, w1R[i].w, w2R[i].z, w2R[i].w);
        }
    };
    auto compute = [&](int buf) {
        ull p1[4] = {0ull, 0ull, 0ull, 0ull};
        ull p2[4] = {0ull, 0ull, 0ull, 0ull};
#pragma unroll
        for (int kk = 0; kk < 32; kk++) {
            float4 a = *(const float4*)&sm.ph.As[buf][kk][r0];
            ulonglong2 w = *(const ulonglong2*)&sm.ph.W12[buf][kk][2 * c0];
            ull a0 = pack2s(a.x), a1 = pack2s(a.y);
            ull a2 = pack2s(a.z), a3 = pack2s(a.w);
            p1[0] = fma2(a0, w.x, p1[0]);
            p2[0] = fma2(a0, w.y, p2[0]);
            p1[1] = fma2(a1, w.x, p1[1]);
            p2[1] = fma2(a1, w.y, p2[1]);
            p1[2] = fma2(a2, w.x, p1[2]);
            p2[2] = fma2(a2, w.y, p2[2]);
            p1[3] = fma2(a3, w.x, p1[3]);
            p2[3] = fma2(a3, w.y, p2[3]);
        }
#pragma unroll
        for (int i = 0; i < 4; i++) {
            acc1[i] = add2(acc1[i], p1[i]);
            acc2[i] = add2(acc2[i], p2[i]);
        }
    };

    // ---- prologue: producers fill stages 0,1 into bufs 0,1 ----
    if (!consumer) {
        float4 aR[2], w1R[2], w2R[2];
        stageLoad(0, aR, w1R, w2R);
        stageStore(0, aR, w1R, w2R);
        stageLoad(1, aR, w1R, w2R);
        stageStore(1, aR, w1R, w2R);
    }
    __syncthreads();

    // ---- mainloop: 2 stages per sync ----
    for (int s = 0; s < nstage; s += 2) {
        if (consumer) {
            compute(s & 3);
            compute((s + 1) & 3);
        } else {
            if (s + 2 < nstage) {
                float4 aR[2], w1R[2], w2R[2];
                float4 aS[2], w1S[2], w2S[2];
                stageLoad(s + 2, aR, w1R, w2R);
                stageLoad(s + 3, aS, w1S, w2S);
                stageStore((s + 2) & 3, aR, w1R, w2R);
                stageStore((s + 3) & 3, aS, w1S, w2S);
            }
        }
        __syncthreads();
    }

    // ---- acc handoff: consumers -> smem ----
    if (consumer) {
#pragma unroll
        for (int i = 0; i < 4; i++) {
            sm.ph.h1[i][ptid] = acc1[i];
            sm.ph.h2[i][ptid] = acc2[i];
        }
    }
    __syncthreads();

    // ---- fp64 epilogue (R4-exact per element), ALL 256 threads, 2 cells each ----
#pragma unroll
    for (int cc = 0; cc < 2; cc++) {
        const int cell = tid * 2 + cc;        // 0..511
        const int wtid = cell >> 2;           // writer consumer ptid
        const int i    = cell & 3;
        const int row  = ((wtid >> 4) << 2) + i;
        const int b    = m0 + row;
        const int nb   = n0 + (wtid & 15) * 2;
        float2 v1 = unpack2(sm.ph.h1[i][wtid]);
        float2 v2 = unpack2(sm.ph.h2[i][wtid]);
        float a1v[2] = {v1.x, v1.y};
        float a2v[2] = {v2.x, v2.y};
#pragma unroll
        for (int c = 0; c < 2; c++) {
            const int n = nb + c;
            if (PHASE == 0) {
                double z = (double)a1v[c] + (double)b1[n]
                         + (double)noise_t[b * DLAT + n];
                float th = (z > 0.0) ? 1.f : 0.f;
                double g  = (z > 0.0) ? tanh(z) : 0.0;
                double hp = zero_h ? 0.0 : (double)h_src[b * DLAT + n];
                double rl = (double)a2v[c] + (double)b2[n];
                float h = (float)(g * tanh(rl) + (1.0 - g) * hp);
                out1[b * DLAT + n]   = h;
                out_th[b * DLAT + n] = th;
            } else {
                double p = (double)a1v[c] + (double)b1[n];
                double o = (double)a2v[c] + (double)b2[n];
                float y = (float)(tanh(p) / (1.0 + exp(-o)));
                out1[b * DLAT + n] = y;
            }
        }
    }
}

// ---------------------------------------------------------------------------
// Persistent megakernel.
// ---------------------------------------------------------------------------
__global__ __launch_bounds__(256, 1) void mega_kernel(
    const float* __restrict__ obs,   const float* __restrict__ smask,
    const float* __restrict__ noise,
    const float* __restrict__ W_pre, const float* __restrict__ b_pre,
    const float* __restrict__ Wg,    const float* __restrict__ bg,
    const float* __restrict__ Wr,    const float* __restrict__ br,
    const float* __restrict__ Wp,    const float* __restrict__ bp,
    const float* __restrict__ Wo,    const float* __restrict__ bo,
    const float* __restrict__ W_out, const float* __restrict__ b_out,
    float* __restrict__ outs, float* __restrict__ hs, float* __restrict__ ths,
    float* __restrict__ ys,   float* __restrict__ dos_)
{
    extern __shared__ char smem_raw[];
    SmemU& sm = *(SmemU*)smem_raw;
    const int tid = threadIdx.x;
    const int blk = blockIdx.x;
    const int b0  = blk * 2;

    // out (+ next-step prep), split-K/split-o reductions (verbatim R11-R14)
    auto do_out_prep = [&](int t, bool do_out, bool do_prep, bool first) {
        auto& op = sm.op;
        if (do_out) {
            const float* y_t = ys + (size_t)t * BB * DLAT;
            {
                int r = tid >> 7, q = tid & 127;
                *(float4*)&op.ysm[r][q * 4] =
                    *(const float4*)&y_t[(size_t)(b0 + r) * 512 + q * 4];
            }
            __syncthreads();
            {
                const int r  = tid >> 7;
                const int fg = (tid >> 4) & 7;
                const int og = tid & 15;
                float4 a = make_float4(0.f, 0.f, 0.f, 0.f);
#pragma unroll 8
                for (int j = 0; j < 64; j++) {
                    const int f = fg * 64 + j;
                    float4 w = *(const float4*)&W_out[(size_t)f * 64 + og * 4];
                    float yv = op.ysm[r][f];
                    a.x += yv * w.x; a.y += yv * w.y;
                    a.z += yv * w.z; a.w += yv * w.w;
                }
                *(float4*)op.opred[r][fg][og] = a;
            }
            __syncthreads();
            if (tid < 128) {
                const int r = tid >> 6, o = tid & 63;
                const int og = o >> 2, c = o & 3;
                float tot = 0.f;
#pragma unroll
                for (int fg = 0; fg < 8; fg++)
                    tot += op.opred[r][fg][og][c];
                tot += b_out[o];
                const int b = b0 + r;
                float outv = g_xin[b * 64 + o] + tot;
                outs[(size_t)t * BB * 64 + b * 64 + o] = outv;
                dos_[(size_t)t * BB * 64 + b * 64 + o] = tot;
                op.outm[r][o] = outv;
            }
            __syncthreads();
        }
        if (do_prep) {
            const int tp = first ? 0 : t + 1;
            if (tid < 128) {
                const int r = tid >> 6, o = tid & 63;
                const int b = b0 + r;
                float m = first ? 1.f
                                : ((smask[(size_t)tp * BB + b] < 0.5f) ? 1.f : 0.f);
                float xin = (m != 0.f) ? obs[(size_t)tp * BB * 64 + b * 64 + o]
                                       : op.outm[r][o];
                g_xin[b * 64 + o] = xin;
                op.xinm[r][o] = xin;
            }
            __syncthreads();
            {
                const int r2 = tid >> 7;
                const int oc = (tid >> 5) & 3;
                const int fg = tid & 31;
                const int f0 = fg * 16;
                float4 a[4];
#pragma unroll
                for (int q = 0; q < 4; q++) a[q] = make_float4(0.f, 0.f, 0.f, 0.f);
#pragma unroll 4
                for (int j = 0; j < 16; j++) {
                    const int o = oc * 16 + j;
                    float xv = op.xinm[r2][o];
#pragma unroll
                    for (int q = 0; q < 4; q++) {
                        float4 w = *(const float4*)&W_pre[(size_t)o * 512 + f0 + q * 4];
                        a[q].x += xv * w.x; a[q].y += xv * w.y;
                        a[q].z += xv * w.z; a[q].w += xv * w.w;
                    }
                }
#pragma unroll
                for (int q = 0; q < 4; q++)
                    *(float4*)&op.pred[r2][oc][f0 + q * 4] = a[q];
            }
            __syncthreads();
            {
                const int r = tid >> 7;
                const int f4 = (tid & 127) * 4;
#pragma unroll
                for (int j = 0; j < 4; j++) {
                    double s = 0.0;
#pragma unroll
                    for (int oc = 0; oc < 4; oc++)
                        s += (double)op.pred[r][oc][f4 + j];
                    g_x[(size_t)(b0 + r) * 512 + f4 + j] =
                        (float)tanh(s + (double)b_pre[f4 + j]);
                }
            }
        }
    };

    do_out_prep(0, false, true, true);
    grid_sync(tid);

    for (int t = 0; t < TS; t++) {
        const float* hprev = hs + (size_t)(t - 1) * BB * DLAT;  // not deref'd at t==0
        float* ht  = hs  + (size_t)t * BB * DLAT;
        float* tht = ths + (size_t)t * BB * DLAT;
        float* yt  = ys  + (size_t)t * BB * DLAT;

        do_phase<0>(sm, blk, t == 0, Wg, bg, Wr, br,
                    noise + (size_t)t * BB * DLAT, hprev, ht, tht);
        grid_sync(tid);

        do_phase<1>(sm, blk, false, Wp, bp, Wo, bo, nullptr, ht, yt, nullptr);
        grid_sync(tid);

        do_out_prep(t, true, t + 1 < TS, false);
        grid_sync(tid);
    }
}

// ---------------------------------------------------------------------------
extern "C" void kernel_launch(void* const* d_in, const int* in_sizes, int n_in,
                              void* d_out, int out_size)
{
    (void)in_sizes; (void)n_in; (void)out_size;
    const float* obs   = (const float*)d_in[0];
    const float* smask = (const float*)d_in[1];
    const float* noise = (const float*)d_in[2];
    const float* W_pre = (const float*)d_in[3];
    const float* b_pre = (const float*)d_in[4];
    const float* Wg    = (const float*)d_in[5];
    const float* bg    = (const float*)d_in[6];
    const float* Wr    = (const float*)d_in[7];
    const float* br    = (const float*)d_in[8];
    const float* Wp    = (const float*)d_in[9];
    const float* bp    = (const float*)d_in[10];
    const float* Wo    = (const float*)d_in[11];
    const float* bo    = (const float*)d_in[12];
    const float* W_out = (const float*)d_in[13];
    const float* b_out = (const float*)d_in[14];

    float* out  = (float*)d_out;
    float* outs = out + OUTS_OFF;
    float* hs   = out + HS_OFF;
    float* ths  = out + TH_OFF;
    float* ys   = out + YS_OFF;
    float* dos_ = out + DO_OFF;

    cudaFuncSetAttribute(mega_kernel,
                         cudaFuncAttributeMaxDynamicSharedMemorySize, SMEM_BYTES);

    mega_kernel<<<NB, 256, SMEM_BYTES>>>(obs, smask, noise,
                                         W_pre, b_pre, Wg, bg, Wr, br,
                                         Wp, bp, Wo, bo, W_out, b_out,
                                         outs, hs, ths, ys, dos_);
}